// round 1
// baseline (speedup 1.0000x reference)
#include <cuda_runtime.h>
#include <math.h>

#define TOK   4096
#define DIM   1024
#define NEXP  8
#define EHID  2816
#define SHID  1536

#define BM 64
#define BN 64
#define BK 16
#define NTHREADS 128

// Scratch (device globals — no allocation allowed)
__device__ float g_h[(size_t)TOK * EHID];   // hidden activations, reused per expert
__device__ int   g_cnt[NEXP];
__device__ int   g_idx[NEXP * TOK];
__device__ float g_wgt[NEXP * TOK];

__global__ void zero_counts_kernel() {
    if (threadIdx.x < NEXP) g_cnt[threadIdx.x] = 0;
}

// One warp per token: compute 8 gate logits, softmax, top-2, compact into
// per-expert (token index, gate weight) lists.
__global__ void gate_kernel(const float* __restrict__ x,
                            const float* __restrict__ gw) {
    int warp = (blockIdx.x * blockDim.x + threadIdx.x) >> 5;
    int lane = threadIdx.x & 31;
    if (warp >= TOK) return;
    const float* xr = x + (size_t)warp * DIM;

    float acc[NEXP];
#pragma unroll
    for (int e = 0; e < NEXP; e++) acc[e] = 0.f;

    for (int d = lane; d < DIM; d += 32) {
        float xv = xr[d];
#pragma unroll
        for (int e = 0; e < NEXP; e++) acc[e] = fmaf(xv, gw[e * DIM + d], acc[e]);
    }
#pragma unroll
    for (int e = 0; e < NEXP; e++) {
#pragma unroll
        for (int off = 16; off > 0; off >>= 1)
            acc[e] += __shfl_xor_sync(0xffffffffu, acc[e], off);
    }
    if (lane == 0) {
        float mx = acc[0];
#pragma unroll
        for (int e = 1; e < NEXP; e++) mx = fmaxf(mx, acc[e]);
        float p[NEXP];
        float s = 0.f;
#pragma unroll
        for (int e = 0; e < NEXP; e++) { p[e] = expf(acc[e] - mx); s += p[e]; }
        float inv = 1.f / s;
#pragma unroll
        for (int e = 0; e < NEXP; e++) p[e] *= inv;

        // top-2 (ties -> lowest index, matching jax.lax.top_k)
        int i1 = 0;
#pragma unroll
        for (int e = 1; e < NEXP; e++) if (p[e] > p[i1]) i1 = e;
        int i2 = (i1 == 0) ? 1 : 0;
#pragma unroll
        for (int e = 0; e < NEXP; e++) if (e != i1 && p[e] > p[i2]) i2 = e;

        int pos1 = atomicAdd(&g_cnt[i1], 1);
        g_idx[i1 * TOK + pos1] = warp;
        g_wgt[i1 * TOK + pos1] = p[i1];
        int pos2 = atomicAdd(&g_cnt[i2], 1);
        g_idx[i2 * TOK + pos2] = warp;
        g_wgt[i2 * TOK + pos2] = p[i2];
    }
}

// Fused SwiGLU up-projection: g_h[m, :N] = silu(A @ B1) * (A @ B3)
// A rows gathered via g_idx[e] when e >= 0 (M = g_cnt[e]); identity when e < 0.
__global__ void __launch_bounds__(NTHREADS)
gemm1_kernel(const float* __restrict__ X,
             const float* __restrict__ B1,
             const float* __restrict__ B3,
             int e, int N, int K) {
    int M = (e >= 0) ? g_cnt[e] : TOK;
    int rowBlock = blockIdx.y * BM;
    if (rowBlock >= M) return;
    int colBlock = blockIdx.x * BN;

    __shared__ float As [BK][BM];
    __shared__ float Bs1[BK][BN];
    __shared__ float Bs3[BK][BN];

    int tid = threadIdx.x;

    // A tile load mapping: 2 threads per row, 8 consecutive k each
    int am    = tid >> 1;
    int akoff = (tid & 1) << 3;
    const float* arow = nullptr;
    {
        int gm = rowBlock + am;
        if (gm < M) {
            int src = (e >= 0) ? g_idx[e * TOK + gm] : gm;
            arow = X + (size_t)src * K + akoff;
        }
    }
    // B tile load mapping: one k-row segment of 8 per thread
    int bk = tid >> 3;
    int bn = (tid & 7) << 3;
    const float* b1p = B1 + (size_t)bk * N + colBlock + bn;
    const float* b3p = B3 + (size_t)bk * N + colBlock + bn;

    int tr = (tid & 15) << 2;   // local row base
    int tc = (tid >> 4) << 3;   // local col base

    float acc1[4][8], acc3[4][8];
#pragma unroll
    for (int i = 0; i < 4; i++)
#pragma unroll
        for (int j = 0; j < 8; j++) { acc1[i][j] = 0.f; acc3[i][j] = 0.f; }

    for (int k0 = 0; k0 < K; k0 += BK) {
        float4 a0 = make_float4(0.f, 0.f, 0.f, 0.f), a1 = a0;
        if (arow) {
            a0 = *reinterpret_cast<const float4*>(arow + k0);
            a1 = *reinterpret_cast<const float4*>(arow + k0 + 4);
        }
        As[akoff + 0][am] = a0.x; As[akoff + 1][am] = a0.y;
        As[akoff + 2][am] = a0.z; As[akoff + 3][am] = a0.w;
        As[akoff + 4][am] = a1.x; As[akoff + 5][am] = a1.y;
        As[akoff + 6][am] = a1.z; As[akoff + 7][am] = a1.w;

        const float* b1k = b1p + (size_t)k0 * N;
        const float* b3k = b3p + (size_t)k0 * N;
        *reinterpret_cast<float4*>(&Bs1[bk][bn])     = *reinterpret_cast<const float4*>(b1k);
        *reinterpret_cast<float4*>(&Bs1[bk][bn + 4]) = *reinterpret_cast<const float4*>(b1k + 4);
        *reinterpret_cast<float4*>(&Bs3[bk][bn])     = *reinterpret_cast<const float4*>(b3k);
        *reinterpret_cast<float4*>(&Bs3[bk][bn + 4]) = *reinterpret_cast<const float4*>(b3k + 4);
        __syncthreads();

#pragma unroll
        for (int k = 0; k < BK; k++) {
            float4 av  = *reinterpret_cast<const float4*>(&As[k][tr]);
            float4 b1a = *reinterpret_cast<const float4*>(&Bs1[k][tc]);
            float4 b1b = *reinterpret_cast<const float4*>(&Bs1[k][tc + 4]);
            float4 b3a = *reinterpret_cast<const float4*>(&Bs3[k][tc]);
            float4 b3b = *reinterpret_cast<const float4*>(&Bs3[k][tc + 4]);
            float a[4]  = {av.x, av.y, av.z, av.w};
            float b1[8] = {b1a.x, b1a.y, b1a.z, b1a.w, b1b.x, b1b.y, b1b.z, b1b.w};
            float b3[8] = {b3a.x, b3a.y, b3a.z, b3a.w, b3b.x, b3b.y, b3b.z, b3b.w};
#pragma unroll
            for (int i = 0; i < 4; i++)
#pragma unroll
                for (int j = 0; j < 8; j++) {
                    acc1[i][j] = fmaf(a[i], b1[j], acc1[i][j]);
                    acc3[i][j] = fmaf(a[i], b3[j], acc3[i][j]);
                }
        }
        __syncthreads();
    }

#pragma unroll
    for (int i = 0; i < 4; i++) {
        int gm = rowBlock + tr + i;
        if (gm >= M) continue;
        float* hrow = g_h + (size_t)gm * N + colBlock + tc;
#pragma unroll
        for (int j = 0; j < 8; j++) {
            float v   = acc1[i][j];
            float sig = 1.f / (1.f + expf(-v));
            hrow[j] = v * sig * acc3[i][j];
        }
    }
}

// Down-projection: OUT[token, :] (+)= w * (g_h[m, :K] @ B2)
// token/weight via g_idx/g_wgt[e] when e >= 0; identity/1.0 when e < 0.
__global__ void __launch_bounds__(NTHREADS)
gemm2_kernel(const float* __restrict__ B2,
             float* __restrict__ OUT,
             int e, int K, int accumulate) {
    int M = (e >= 0) ? g_cnt[e] : TOK;
    int rowBlock = blockIdx.y * BM;
    if (rowBlock >= M) return;
    int colBlock = blockIdx.x * BN;

    __shared__ float As[BK][BM];
    __shared__ float Bs[BK][BN];

    int tid = threadIdx.x;

    int am    = tid >> 1;
    int akoff = (tid & 1) << 3;
    const float* arow = nullptr;
    {
        int gm = rowBlock + am;
        if (gm < M) arow = g_h + (size_t)gm * K + akoff;
    }
    int bk = tid >> 3;
    int bn = (tid & 7) << 3;
    const float* bp = B2 + (size_t)bk * DIM + colBlock + bn;

    int tr = (tid & 15) << 2;
    int tc = (tid >> 4) << 3;

    float acc[4][8];
#pragma unroll
    for (int i = 0; i < 4; i++)
#pragma unroll
        for (int j = 0; j < 8; j++) acc[i][j] = 0.f;

    for (int k0 = 0; k0 < K; k0 += BK) {
        float4 a0 = make_float4(0.f, 0.f, 0.f, 0.f), a1 = a0;
        if (arow) {
            a0 = *reinterpret_cast<const float4*>(arow + k0);
            a1 = *reinterpret_cast<const float4*>(arow + k0 + 4);
        }
        As[akoff + 0][am] = a0.x; As[akoff + 1][am] = a0.y;
        As[akoff + 2][am] = a0.z; As[akoff + 3][am] = a0.w;
        As[akoff + 4][am] = a1.x; As[akoff + 5][am] = a1.y;
        As[akoff + 6][am] = a1.z; As[akoff + 7][am] = a1.w;

        const float* bkp = bp + (size_t)k0 * DIM;
        *reinterpret_cast<float4*>(&Bs[bk][bn])     = *reinterpret_cast<const float4*>(bkp);
        *reinterpret_cast<float4*>(&Bs[bk][bn + 4]) = *reinterpret_cast<const float4*>(bkp + 4);
        __syncthreads();

#pragma unroll
        for (int k = 0; k < BK; k++) {
            float4 av = *reinterpret_cast<const float4*>(&As[k][tr]);
            float4 ba = *reinterpret_cast<const float4*>(&Bs[k][tc]);
            float4 bb = *reinterpret_cast<const float4*>(&Bs[k][tc + 4]);
            float a[4] = {av.x, av.y, av.z, av.w};
            float b[8] = {ba.x, ba.y, ba.z, ba.w, bb.x, bb.y, bb.z, bb.w};
#pragma unroll
            for (int i = 0; i < 4; i++)
#pragma unroll
                for (int j = 0; j < 8; j++)
                    acc[i][j] = fmaf(a[i], b[j], acc[i][j]);
        }
        __syncthreads();
    }

#pragma unroll
    for (int i = 0; i < 4; i++) {
        int gm = rowBlock + tr + i;
        if (gm >= M) continue;
        int   token;
        float w;
        if (e >= 0) { token = g_idx[e * TOK + gm]; w = g_wgt[e * TOK + gm]; }
        else        { token = gm;                  w = 1.f; }
        float* orow = OUT + (size_t)token * DIM + colBlock + tc;
        if (accumulate) {
#pragma unroll
            for (int j = 0; j < 8; j++) orow[j] += w * acc[i][j];
        } else {
#pragma unroll
            for (int j = 0; j < 8; j++) orow[j] = acc[i][j];
        }
    }
}

extern "C" void kernel_launch(void* const* d_in, const int* in_sizes, int n_in,
                              void* d_out, int out_size) {
    const float* x   = (const float*)d_in[0];
    const float* gw  = (const float*)d_in[1];
    const float* w1  = (const float*)d_in[2];
    const float* w2  = (const float*)d_in[3];
    const float* w3  = (const float*)d_in[4];
    const float* sw1 = (const float*)d_in[5];
    const float* sw2 = (const float*)d_in[6];
    const float* sw3 = (const float*)d_in[7];
    float* out = (float*)d_out;
    (void)in_sizes; (void)n_in; (void)out_size;

    zero_counts_kernel<<<1, 32>>>();
    gate_kernel<<<TOK / 8, 256>>>(x, gw);

    // Shared expert first: its down-proj STORES (initializes) d_out.
    {
        dim3 g1(SHID / BN, TOK / BM);
        gemm1_kernel<<<g1, NTHREADS>>>(x, sw1, sw3, -1, SHID, DIM);
        dim3 g2(DIM / BN, TOK / BM);
        gemm2_kernel<<<g2, NTHREADS>>>(sw2, out, -1, SHID, 0);
    }

    // Routed experts: gathered up-proj, scatter-add down-proj.
    dim3 g1r(EHID / BN, TOK / BM);
    dim3 g2r(DIM / BN, TOK / BM);
    for (int ex = 0; ex < NEXP; ex++) {
        gemm1_kernel<<<g1r, NTHREADS>>>(x,
                                        w1 + (size_t)ex * DIM * EHID,
                                        w3 + (size_t)ex * DIM * EHID,
                                        ex, EHID, DIM);
        gemm2_kernel<<<g2r, NTHREADS>>>(w2 + (size_t)ex * EHID * DIM,
                                        out, ex, EHID, 1);
    }
}

// round 2
// speedup vs baseline: 2.5946x; 2.5946x over previous
#include <cuda_runtime.h>
#include <cuda_bf16.h>
#include <math.h>
#include <stdint.h>

#define TOK   4096
#define DIM   1024
#define NEXP  8
#define EHID  2816
#define SHID  1536
#define LDA   36    // padded smem row stride in 4B words for BK=32

// ---------------- scratch (device globals; no runtime allocation) ----------
__device__ uint32_t g_xc [(size_t)TOK*DIM];          // x as packed (bf16 hi, bf16 lo)
__device__ uint32_t g_w1t[(size_t)NEXP*EHID*DIM];    // [e][N][K] transposed, packed
__device__ uint32_t g_w3t[(size_t)NEXP*EHID*DIM];
__device__ uint32_t g_w2t[(size_t)NEXP*DIM*EHID];
__device__ uint32_t g_sw1t[(size_t)SHID*DIM];
__device__ uint32_t g_sw3t[(size_t)SHID*DIM];
__device__ uint32_t g_sw2t[(size_t)DIM*SHID];
__device__ uint32_t g_hc [(size_t)NEXP*TOK*EHID];    // routed hidden, packed
__device__ uint32_t g_hs [(size_t)TOK*SHID];         // shared hidden, packed
__device__ float    g_yp [(size_t)NEXP*TOK*DIM];     // routed partial outputs
__device__ int      g_cnt[NEXP];
__device__ int      g_idx[NEXP*TOK];
__device__ float    g_wgt[NEXP*TOK];
__device__ int      g_slot[TOK*2];

// ---------------- helpers ---------------------------------------------------
__device__ __forceinline__ uint32_t f2bf2(float v) {
    __nv_bfloat16 h = __float2bfloat16(v);
    float r = v - __bfloat162float(h);
    __nv_bfloat16 l = __float2bfloat16(r);
    return ((uint32_t)__bfloat16_as_ushort(l) << 16) | (uint32_t)__bfloat16_as_ushort(h);
}

__device__ __forceinline__ void mma_bf16(float d[4],
        uint32_t a0, uint32_t a1, uint32_t a2, uint32_t a3,
        uint32_t b0, uint32_t b1) {
    asm volatile(
        "mma.sync.aligned.m16n8k16.row.col.f32.bf16.bf16.f32 "
        "{%0,%1,%2,%3},{%4,%5,%6,%7},{%8,%9},{%0,%1,%2,%3};"
        : "+f"(d[0]), "+f"(d[1]), "+f"(d[2]), "+f"(d[3])
        : "r"(a0), "r"(a1), "r"(a2), "r"(a3), "r"(b0), "r"(b1));
}

__device__ __forceinline__ void cp16(uint32_t saddr, const void* g, bool valid) {
    int sz = valid ? 16 : 0;
    asm volatile("cp.async.cg.shared.global [%0], [%1], 16, %2;"
                 :: "r"(saddr), "l"(g), "r"(sz));
}
#define CP_COMMIT() asm volatile("cp.async.commit_group;")
#define CP_WAIT1()  asm volatile("cp.async.wait_group 1;")
#define CP_WAIT0()  asm volatile("cp.async.wait_group 0;")

// ---------------- small kernels ---------------------------------------------
__global__ void zero_counts_kernel() {
    if (threadIdx.x < NEXP) g_cnt[threadIdx.x] = 0;
}

// elementwise convert x -> packed hi/lo
__global__ void cvtx_kernel(const float* __restrict__ in, uint32_t* __restrict__ out, int n4) {
    int i = blockIdx.x * blockDim.x + threadIdx.x;
    if (i < n4) {
        float4 v = reinterpret_cast<const float4*>(in)[i];
        uint4 o;
        o.x = f2bf2(v.x); o.y = f2bf2(v.y); o.z = f2bf2(v.z); o.w = f2bf2(v.w);
        reinterpret_cast<uint4*>(out)[i] = o;
    }
}

// transpose+convert: in [z][K][N] fp32 -> out [z][N][K] packed
__global__ void cvtT_kernel(const float* __restrict__ in, uint32_t* __restrict__ out,
                            int K, int N) {
    __shared__ float tile[32][33];
    size_t z = blockIdx.z;
    in  += z * (size_t)K * N;
    out += z * (size_t)N * K;
    int k0 = blockIdx.y * 32, n0 = blockIdx.x * 32;
    int tx = threadIdx.x, ty = threadIdx.y;   // 32 x 8
#pragma unroll
    for (int i = 0; i < 32; i += 8)
        tile[ty + i][tx] = in[(size_t)(k0 + ty + i) * N + (n0 + tx)];
    __syncthreads();
#pragma unroll
    for (int i = 0; i < 32; i += 8)
        out[(size_t)(n0 + ty + i) * K + (k0 + tx)] = f2bf2(tile[tx][ty + i]);
}

// one warp per token: softmax over 8 logits, top-2, compact
__global__ void gate_kernel(const float* __restrict__ x, const float* __restrict__ gw) {
    int tok  = (blockIdx.x * blockDim.x + threadIdx.x) >> 5;
    int lane = threadIdx.x & 31;
    if (tok >= TOK) return;
    const float* xr = x + (size_t)tok * DIM;
    float acc[NEXP];
#pragma unroll
    for (int e = 0; e < NEXP; e++) acc[e] = 0.f;
    for (int d = lane; d < DIM; d += 32) {
        float xv = xr[d];
#pragma unroll
        for (int e = 0; e < NEXP; e++) acc[e] = fmaf(xv, gw[e * DIM + d], acc[e]);
    }
#pragma unroll
    for (int e = 0; e < NEXP; e++)
#pragma unroll
        for (int off = 16; off > 0; off >>= 1)
            acc[e] += __shfl_xor_sync(0xffffffffu, acc[e], off);
    if (lane == 0) {
        float mx = acc[0];
#pragma unroll
        for (int e = 1; e < NEXP; e++) mx = fmaxf(mx, acc[e]);
        float p[NEXP], s = 0.f;
#pragma unroll
        for (int e = 0; e < NEXP; e++) { p[e] = expf(acc[e] - mx); s += p[e]; }
        float inv = 1.f / s;
#pragma unroll
        for (int e = 0; e < NEXP; e++) p[e] *= inv;
        int i1 = 0;
#pragma unroll
        for (int e = 1; e < NEXP; e++) if (p[e] > p[i1]) i1 = e;
        int i2 = (i1 == 0) ? 1 : 0;
#pragma unroll
        for (int e = 0; e < NEXP; e++) if (e != i1 && p[e] > p[i2]) i2 = e;
        int pos1 = atomicAdd(&g_cnt[i1], 1);
        g_idx[i1 * TOK + pos1] = tok;  g_wgt[i1 * TOK + pos1] = p[i1];
        g_slot[2 * tok]     = i1 * TOK + pos1;
        int pos2 = atomicAdd(&g_cnt[i2], 1);
        g_idx[i2 * TOK + pos2] = tok;  g_wgt[i2 * TOK + pos2] = p[i2];
        g_slot[2 * tok + 1] = i2 * TOK + pos2;
    }
}

// ---------------- GEMM 1: fused SwiGLU up-projection -------------------------
// H[m, :N] = split( silu(A@B1) * (A@B3) ),  A gathered rows of g_xc, K = DIM.
// BM=128, BN=64, BK=32, 256 threads, 8 warps (2m x 4n), warp tile 64x16.
__global__ void __launch_bounds__(256, 1)
gemm1_kernel(const uint32_t* __restrict__ Xc,
             const uint32_t* __restrict__ B1,
             const uint32_t* __restrict__ B3,
             uint32_t* __restrict__ H,
             int routed, int N) {
    const int K = DIM;
    int e = routed ? (int)blockIdx.z : -1;
    int M = routed ? g_cnt[e] : TOK;
    int rowBlock = blockIdx.y * 128;
    if (rowBlock >= M) return;
    int colBlock = blockIdx.x * 64;
    if (routed) {
        size_t wo = (size_t)e * N * K;
        B1 += wo;  B3 += wo;  H += (size_t)e * TOK * N;
    }

    extern __shared__ __align__(16) uint32_t smem[];
    uint32_t* As  = smem;                    // [2][128][LDA]
    uint32_t* B1s = As  + 2 * 128 * LDA;     // [2][64][LDA]
    uint32_t* B3s = B1s + 2 * 64  * LDA;

    int tid = threadIdx.x;
    int lane = tid & 31, warp = tid >> 5;
    int wm = warp >> 2, wn = warp & 3;
    int lq = lane >> 2, lr = lane & 3;
    int chunk = tid & 7;                     // 16B chunk within a 128B k-row

    // per-thread global source pointers
    const uint32_t* aptr[4]; bool aval[4];
#pragma unroll
    for (int it = 0; it < 4; it++) {
        int m  = (tid >> 3) + it * 32;
        int gm = rowBlock + m;
        bool v = gm < M;
        int src = v ? (routed ? g_idx[e * TOK + gm] : gm) : 0;
        aptr[it] = Xc + (size_t)src * K + chunk * 4;
        aval[it] = v;
    }
    const uint32_t *b1p[2], *b3p[2];
#pragma unroll
    for (int it = 0; it < 2; it++) {
        int n = (tid >> 3) + it * 32;
        b1p[it] = B1 + (size_t)(colBlock + n) * K + chunk * 4;
        b3p[it] = B3 + (size_t)(colBlock + n) * K + chunk * 4;
    }

    uint32_t sA  = (uint32_t)__cvta_generic_to_shared(As);
    uint32_t sB1 = (uint32_t)__cvta_generic_to_shared(B1s);
    uint32_t sB3 = (uint32_t)__cvta_generic_to_shared(B3s);

    auto load_stage = [&](int buf, int k0) {
#pragma unroll
        for (int it = 0; it < 4; it++) {
            int m = (tid >> 3) + it * 32;
            cp16(sA + (uint32_t)(((buf * 128 + m) * LDA + chunk * 4) * 4),
                 aptr[it] + k0, aval[it]);
        }
#pragma unroll
        for (int it = 0; it < 2; it++) {
            int n = (tid >> 3) + it * 32;
            cp16(sB1 + (uint32_t)(((buf * 64 + n) * LDA + chunk * 4) * 4),
                 b1p[it] + k0, true);
            cp16(sB3 + (uint32_t)(((buf * 64 + n) * LDA + chunk * 4) * 4),
                 b3p[it] + k0, true);
        }
    };

    float acc1[4][2][4], acc3[4][2][4];
#pragma unroll
    for (int i = 0; i < 4; i++)
#pragma unroll
        for (int j = 0; j < 2; j++)
#pragma unroll
            for (int r = 0; r < 4; r++) { acc1[i][j][r] = 0.f; acc3[i][j][r] = 0.f; }

    load_stage(0, 0);
    CP_COMMIT();
    const int nIter = K / 32;
    for (int i = 0; i < nIter; i++) {
        if (i + 1 < nIter) { load_stage((i + 1) & 1, (i + 1) * 32); CP_COMMIT(); CP_WAIT1(); }
        else               { CP_WAIT0(); }
        __syncthreads();
        const uint32_t* Ab  = As  + (i & 1) * 128 * LDA;
        const uint32_t* B1b = B1s + (i & 1) * 64 * LDA;
        const uint32_t* B3b = B3s + (i & 1) * 64 * LDA;
#pragma unroll
        for (int ks = 0; ks < 2; ks++) {
            int kb = ks * 16 + 2 * lr;
            uint32_t ah[4][4], al[4][4];
#pragma unroll
            for (int mi = 0; mi < 4; mi++) {
                int r = wm * 64 + mi * 16 + lq;
                uint32_t u0 = Ab[r * LDA + kb],       u1 = Ab[r * LDA + kb + 1];
                uint32_t u2 = Ab[(r + 8) * LDA + kb], u3 = Ab[(r + 8) * LDA + kb + 1];
                uint32_t u4 = Ab[r * LDA + kb + 8],   u5 = Ab[r * LDA + kb + 9];
                uint32_t u6 = Ab[(r + 8) * LDA + kb + 8], u7 = Ab[(r + 8) * LDA + kb + 9];
                ah[mi][0] = __byte_perm(u0, u1, 0x5410); al[mi][0] = __byte_perm(u0, u1, 0x7632);
                ah[mi][1] = __byte_perm(u2, u3, 0x5410); al[mi][1] = __byte_perm(u2, u3, 0x7632);
                ah[mi][2] = __byte_perm(u4, u5, 0x5410); al[mi][2] = __byte_perm(u4, u5, 0x7632);
                ah[mi][3] = __byte_perm(u6, u7, 0x5410); al[mi][3] = __byte_perm(u6, u7, 0x7632);
            }
            uint32_t b1h[2][2], b1l[2][2], b3h[2][2], b3l[2][2];
#pragma unroll
            for (int ni = 0; ni < 2; ni++) {
                int n = wn * 16 + ni * 8 + lq;
                uint32_t u0 = B1b[n * LDA + kb],     u1 = B1b[n * LDA + kb + 1];
                uint32_t u2 = B1b[n * LDA + kb + 8], u3 = B1b[n * LDA + kb + 9];
                b1h[ni][0] = __byte_perm(u0, u1, 0x5410); b1l[ni][0] = __byte_perm(u0, u1, 0x7632);
                b1h[ni][1] = __byte_perm(u2, u3, 0x5410); b1l[ni][1] = __byte_perm(u2, u3, 0x7632);
                u0 = B3b[n * LDA + kb];     u1 = B3b[n * LDA + kb + 1];
                u2 = B3b[n * LDA + kb + 8]; u3 = B3b[n * LDA + kb + 9];
                b3h[ni][0] = __byte_perm(u0, u1, 0x5410); b3l[ni][0] = __byte_perm(u0, u1, 0x7632);
                b3h[ni][1] = __byte_perm(u2, u3, 0x5410); b3l[ni][1] = __byte_perm(u2, u3, 0x7632);
            }
#pragma unroll
            for (int mi = 0; mi < 4; mi++)
#pragma unroll
                for (int ni = 0; ni < 2; ni++) {
                    mma_bf16(acc1[mi][ni], ah[mi][0], ah[mi][1], ah[mi][2], ah[mi][3], b1h[ni][0], b1h[ni][1]);
                    mma_bf16(acc1[mi][ni], ah[mi][0], ah[mi][1], ah[mi][2], ah[mi][3], b1l[ni][0], b1l[ni][1]);
                    mma_bf16(acc1[mi][ni], al[mi][0], al[mi][1], al[mi][2], al[mi][3], b1h[ni][0], b1h[ni][1]);
                    mma_bf16(acc3[mi][ni], ah[mi][0], ah[mi][1], ah[mi][2], ah[mi][3], b3h[ni][0], b3h[ni][1]);
                    mma_bf16(acc3[mi][ni], ah[mi][0], ah[mi][1], ah[mi][2], ah[mi][3], b3l[ni][0], b3l[ni][1]);
                    mma_bf16(acc3[mi][ni], al[mi][0], al[mi][1], al[mi][2], al[mi][3], b3h[ni][0], b3h[ni][1]);
                }
        }
        __syncthreads();
    }

    // epilogue: silu(acc1)*acc3, split, store packed
#pragma unroll
    for (int mi = 0; mi < 4; mi++) {
        int rbase = rowBlock + wm * 64 + mi * 16 + lq;
#pragma unroll
        for (int ni = 0; ni < 2; ni++) {
            int c = colBlock + wn * 16 + ni * 8 + 2 * lr;
#pragma unroll
            for (int half = 0; half < 2; half++) {
                int gm = rbase + half * 8;
                if (gm < M) {
                    float v1a = acc1[mi][ni][half * 2], v1b = acc1[mi][ni][half * 2 + 1];
                    float v3a = acc3[mi][ni][half * 2], v3b = acc3[mi][ni][half * 2 + 1];
                    float h0 = v1a / (1.f + expf(-v1a)) * v3a;
                    float h1 = v1b / (1.f + expf(-v1b)) * v3b;
                    uint2 pv; pv.x = f2bf2(h0); pv.y = f2bf2(h1);
                    *reinterpret_cast<uint2*>(H + (size_t)gm * N + c) = pv;
                }
            }
        }
    }
}

// ---------------- GEMM 2: down-projection -----------------------------------
// Y[m, :DIM] = w[m] * (A @ B2),  A = hidden (packed), B2 transposed [DIM][K].
// BM=128, BN=128, BK=32, 256 threads, 8 warps (2m x 4n), warp tile 64x32.
__global__ void __launch_bounds__(256, 1)
gemm2_kernel(const uint32_t* __restrict__ Hin,
             const uint32_t* __restrict__ B2,
             float* __restrict__ Y,
             int routed, int K) {
    int e = routed ? (int)blockIdx.z : -1;
    int M = routed ? g_cnt[e] : TOK;
    int rowBlock = blockIdx.y * 128;
    if (rowBlock >= M) return;
    int colBlock = blockIdx.x * 128;
    if (routed) {
        Hin += (size_t)e * TOK * K;
        B2  += (size_t)e * DIM * K;
        Y   += (size_t)e * TOK * DIM;
    }

    extern __shared__ __align__(16) uint32_t smem[];
    uint32_t* As = smem;                 // [2][128][LDA]
    uint32_t* Bs = As + 2 * 128 * LDA;   // [2][128][LDA]

    int tid = threadIdx.x;
    int lane = tid & 31, warp = tid >> 5;
    int wm = warp >> 2, wn = warp & 3;
    int lq = lane >> 2, lr = lane & 3;
    int chunk = tid & 7;

    const uint32_t* aptr[4]; bool aval[4];
    const uint32_t* bptr[4];
#pragma unroll
    for (int it = 0; it < 4; it++) {
        int m  = (tid >> 3) + it * 32;
        int gm = rowBlock + m;
        aval[it] = gm < M;
        aptr[it] = Hin + (size_t)(aval[it] ? gm : 0) * K + chunk * 4;
        bptr[it] = B2 + (size_t)(colBlock + m) * K + chunk * 4;
    }

    uint32_t sA = (uint32_t)__cvta_generic_to_shared(As);
    uint32_t sB = (uint32_t)__cvta_generic_to_shared(Bs);

    auto load_stage = [&](int buf, int k0) {
#pragma unroll
        for (int it = 0; it < 4; it++) {
            int m = (tid >> 3) + it * 32;
            cp16(sA + (uint32_t)(((buf * 128 + m) * LDA + chunk * 4) * 4),
                 aptr[it] + k0, aval[it]);
            cp16(sB + (uint32_t)(((buf * 128 + m) * LDA + chunk * 4) * 4),
                 bptr[it] + k0, true);
        }
    };

    float acc[4][4][4];
#pragma unroll
    for (int i = 0; i < 4; i++)
#pragma unroll
        for (int j = 0; j < 4; j++)
#pragma unroll
            for (int r = 0; r < 4; r++) acc[i][j][r] = 0.f;

    load_stage(0, 0);
    CP_COMMIT();
    const int nIter = K / 32;
    for (int i = 0; i < nIter; i++) {
        if (i + 1 < nIter) { load_stage((i + 1) & 1, (i + 1) * 32); CP_COMMIT(); CP_WAIT1(); }
        else               { CP_WAIT0(); }
        __syncthreads();
        const uint32_t* Ab = As + (i & 1) * 128 * LDA;
        const uint32_t* Bb = Bs + (i & 1) * 128 * LDA;
#pragma unroll
        for (int ks = 0; ks < 2; ks++) {
            int kb = ks * 16 + 2 * lr;
            uint32_t ah[4][4], al[4][4];
#pragma unroll
            for (int mi = 0; mi < 4; mi++) {
                int r = wm * 64 + mi * 16 + lq;
                uint32_t u0 = Ab[r * LDA + kb],       u1 = Ab[r * LDA + kb + 1];
                uint32_t u2 = Ab[(r + 8) * LDA + kb], u3 = Ab[(r + 8) * LDA + kb + 1];
                uint32_t u4 = Ab[r * LDA + kb + 8],   u5 = Ab[r * LDA + kb + 9];
                uint32_t u6 = Ab[(r + 8) * LDA + kb + 8], u7 = Ab[(r + 8) * LDA + kb + 9];
                ah[mi][0] = __byte_perm(u0, u1, 0x5410); al[mi][0] = __byte_perm(u0, u1, 0x7632);
                ah[mi][1] = __byte_perm(u2, u3, 0x5410); al[mi][1] = __byte_perm(u2, u3, 0x7632);
                ah[mi][2] = __byte_perm(u4, u5, 0x5410); al[mi][2] = __byte_perm(u4, u5, 0x7632);
                ah[mi][3] = __byte_perm(u6, u7, 0x5410); al[mi][3] = __byte_perm(u6, u7, 0x7632);
            }
            uint32_t bh[4][2], bl[4][2];
#pragma unroll
            for (int ni = 0; ni < 4; ni++) {
                int n = wn * 32 + ni * 8 + lq;
                uint32_t u0 = Bb[n * LDA + kb],     u1 = Bb[n * LDA + kb + 1];
                uint32_t u2 = Bb[n * LDA + kb + 8], u3 = Bb[n * LDA + kb + 9];
                bh[ni][0] = __byte_perm(u0, u1, 0x5410); bl[ni][0] = __byte_perm(u0, u1, 0x7632);
                bh[ni][1] = __byte_perm(u2, u3, 0x5410); bl[ni][1] = __byte_perm(u2, u3, 0x7632);
            }
#pragma unroll
            for (int mi = 0; mi < 4; mi++)
#pragma unroll
                for (int ni = 0; ni < 4; ni++) {
                    mma_bf16(acc[mi][ni], ah[mi][0], ah[mi][1], ah[mi][2], ah[mi][3], bh[ni][0], bh[ni][1]);
                    mma_bf16(acc[mi][ni], ah[mi][0], ah[mi][1], ah[mi][2], ah[mi][3], bl[ni][0], bl[ni][1]);
                    mma_bf16(acc[mi][ni], al[mi][0], al[mi][1], al[mi][2], al[mi][3], bh[ni][0], bh[ni][1]);
                }
        }
        __syncthreads();
    }

#pragma unroll
    for (int mi = 0; mi < 4; mi++) {
        int rbase = rowBlock + wm * 64 + mi * 16 + lq;
#pragma unroll
        for (int half = 0; half < 2; half++) {
            int gm = rbase + half * 8;
            if (gm < M) {
                float w = routed ? g_wgt[e * TOK + gm] : 1.0f;
#pragma unroll
                for (int ni = 0; ni < 4; ni++) {
                    int c = colBlock + wn * 32 + ni * 8 + 2 * lr;
                    float2 v;
                    v.x = w * acc[mi][ni][half * 2];
                    v.y = w * acc[mi][ni][half * 2 + 1];
                    *reinterpret_cast<float2*>(Y + (size_t)gm * DIM + c) = v;
                }
            }
        }
    }
}

// out[t] += y_part[slot0(t)] + y_part[slot1(t)]
__global__ void combine_kernel(float* __restrict__ out) {
    int t = blockIdx.x;
    int d = threadIdx.x;   // 256 threads x float4 = 1024 floats
    int s0 = g_slot[2 * t], s1 = g_slot[2 * t + 1];
    float4* o = reinterpret_cast<float4*>(out) + (size_t)t * 256 + d;
    const float4 a = *o;
    const float4 b0 = reinterpret_cast<const float4*>(g_yp)[(size_t)s0 * 256 + d];
    const float4 b1 = reinterpret_cast<const float4*>(g_yp)[(size_t)s1 * 256 + d];
    float4 r;
    r.x = a.x + (b0.x + b1.x);
    r.y = a.y + (b0.y + b1.y);
    r.z = a.z + (b0.z + b1.z);
    r.w = a.w + (b0.w + b1.w);
    *o = r;
}

// ---------------- launcher ---------------------------------------------------
extern "C" void kernel_launch(void* const* d_in, const int* in_sizes, int n_in,
                              void* d_out, int out_size) {
    const float* x   = (const float*)d_in[0];
    const float* gw  = (const float*)d_in[1];
    const float* w1  = (const float*)d_in[2];
    const float* w2  = (const float*)d_in[3];
    const float* w3  = (const float*)d_in[4];
    const float* sw1 = (const float*)d_in[5];
    const float* sw2 = (const float*)d_in[6];
    const float* sw3 = (const float*)d_in[7];
    float* out = (float*)d_out;
    (void)in_sizes; (void)n_in; (void)out_size;

    const int SMEM1 = (2 * 128 * LDA + 2 * 2 * 64 * LDA) * 4;   // 73728 B
    const int SMEM2 = (2 * 128 * LDA + 2 * 128 * LDA) * 4;      // 73728 B
    cudaFuncSetAttribute(gemm1_kernel, cudaFuncAttributeMaxDynamicSharedMemorySize, SMEM1);
    cudaFuncSetAttribute(gemm2_kernel, cudaFuncAttributeMaxDynamicSharedMemorySize, SMEM2);

    uint32_t *xc, *w1t, *w3t, *w2t, *sw1t, *sw3t, *sw2t, *hc, *hs;
    float* yp;
    cudaGetSymbolAddress((void**)&xc,  g_xc);
    cudaGetSymbolAddress((void**)&w1t, g_w1t);
    cudaGetSymbolAddress((void**)&w3t, g_w3t);
    cudaGetSymbolAddress((void**)&w2t, g_w2t);
    cudaGetSymbolAddress((void**)&sw1t, g_sw1t);
    cudaGetSymbolAddress((void**)&sw3t, g_sw3t);
    cudaGetSymbolAddress((void**)&sw2t, g_sw2t);
    cudaGetSymbolAddress((void**)&hc,  g_hc);
    cudaGetSymbolAddress((void**)&hs,  g_hs);
    cudaGetSymbolAddress((void**)&yp,  g_yp);

    zero_counts_kernel<<<1, 32>>>();
    cvtx_kernel<<<(TOK * DIM / 4 + 255) / 256, 256>>>(x, xc, TOK * DIM / 4);
    cvtT_kernel<<<dim3(EHID / 32, DIM / 32, NEXP), dim3(32, 8)>>>(w1, w1t, DIM, EHID);
    cvtT_kernel<<<dim3(EHID / 32, DIM / 32, NEXP), dim3(32, 8)>>>(w3, w3t, DIM, EHID);
    cvtT_kernel<<<dim3(DIM / 32, EHID / 32, NEXP), dim3(32, 8)>>>(w2, w2t, EHID, DIM);
    cvtT_kernel<<<dim3(SHID / 32, DIM / 32, 1),  dim3(32, 8)>>>(sw1, sw1t, DIM, SHID);
    cvtT_kernel<<<dim3(SHID / 32, DIM / 32, 1),  dim3(32, 8)>>>(sw3, sw3t, DIM, SHID);
    cvtT_kernel<<<dim3(DIM / 32, SHID / 32, 1),  dim3(32, 8)>>>(sw2, sw2t, SHID, DIM);
    gate_kernel<<<TOK / 8, 256>>>(x, gw);

    // shared expert (writes d_out)
    gemm1_kernel<<<dim3(SHID / 64, TOK / 128, 1), 256, SMEM1>>>(xc, sw1t, sw3t, hs, 0, SHID);
    gemm2_kernel<<<dim3(DIM / 128, TOK / 128, 1), 256, SMEM2>>>(hs, sw2t, out, 0, SHID);

    // routed experts, batched over grid.z
    gemm1_kernel<<<dim3(EHID / 64, TOK / 128, NEXP), 256, SMEM1>>>(xc, w1t, w3t, hc, 1, EHID);
    gemm2_kernel<<<dim3(DIM / 128, TOK / 128, NEXP), 256, SMEM2>>>(hc, w2t, yp, 1, EHID);

    combine_kernel<<<TOK, 256>>>(out);
}

// round 4
// speedup vs baseline: 2.6596x; 1.0250x over previous
#include <cuda_runtime.h>
#include <cuda_bf16.h>
#include <math.h>
#include <stdint.h>

#define TOK   4096
#define DIM   1024
#define NEXP  8
#define EHID  2816
#define SHID  1536
#define LDH   40      // smem row stride in bf16 elems (32 data + 8 pad)

typedef __nv_bfloat16 bf16;

// ---------------- scratch (device globals) ----------------------------------
__device__ bf16  g_xh [(size_t)TOK*DIM];
__device__ bf16  g_xl [(size_t)TOK*DIM];
__device__ bf16  g_w1h[(size_t)NEXP*EHID*DIM];
__device__ bf16  g_w1l[(size_t)NEXP*EHID*DIM];
__device__ bf16  g_w3h[(size_t)NEXP*EHID*DIM];
__device__ bf16  g_w3l[(size_t)NEXP*EHID*DIM];
__device__ bf16  g_w2h[(size_t)NEXP*DIM*EHID];
__device__ bf16  g_w2l[(size_t)NEXP*DIM*EHID];
__device__ bf16  g_s1h[(size_t)SHID*DIM];
__device__ bf16  g_s1l[(size_t)SHID*DIM];
__device__ bf16  g_s3h[(size_t)SHID*DIM];
__device__ bf16  g_s3l[(size_t)SHID*DIM];
__device__ bf16  g_s2h[(size_t)DIM*SHID];
__device__ bf16  g_s2l[(size_t)DIM*SHID];
__device__ bf16  g_hh [(size_t)NEXP*TOK*EHID];
__device__ bf16  g_hl [(size_t)NEXP*TOK*EHID];
__device__ bf16  g_hsh[(size_t)TOK*SHID];
__device__ bf16  g_hsl[(size_t)TOK*SHID];
__device__ float g_yp [(size_t)NEXP*TOK*DIM];
__device__ int   g_cnt[NEXP];
__device__ int   g_idx[NEXP*TOK];
__device__ float g_wgt[NEXP*TOK];
__device__ int   g_slot[TOK*2];

// ---------------- helpers ----------------------------------------------------
__device__ __forceinline__ uint32_t smem_u32(const void* p) {
    uint32_t a;
    asm("{ .reg .u64 t; cvta.to.shared.u64 t, %1; cvt.u32.u64 %0, t; }"
        : "=r"(a) : "l"(p));
    return a;
}
__device__ __forceinline__ void cp16(uint32_t saddr, const void* g, bool valid) {
    int sz = valid ? 16 : 0;
    asm volatile("cp.async.cg.shared.global [%0], [%1], 16, %2;"
                 :: "r"(saddr), "l"(g), "r"(sz));
}
#define CP_COMMIT() asm volatile("cp.async.commit_group;")
#define CP_WAIT1()  asm volatile("cp.async.wait_group 1;")
#define CP_WAIT0()  asm volatile("cp.async.wait_group 0;")

#define LDSM4(r, addr) \
    asm volatile("ldmatrix.sync.aligned.m8n8.x4.shared.b16 {%0,%1,%2,%3}, [%4];" \
        : "=r"((r)[0]), "=r"((r)[1]), "=r"((r)[2]), "=r"((r)[3]) : "r"(addr))

__device__ __forceinline__ void mma_bf16(float d[4], const uint32_t a[4],
                                         uint32_t b0, uint32_t b1) {
    asm volatile(
        "mma.sync.aligned.m16n8k16.row.col.f32.bf16.bf16.f32 "
        "{%0,%1,%2,%3},{%4,%5,%6,%7},{%8,%9},{%0,%1,%2,%3};"
        : "+f"(d[0]), "+f"(d[1]), "+f"(d[2]), "+f"(d[3])
        : "r"(a[0]), "r"(a[1]), "r"(a[2]), "r"(a[3]), "r"(b0), "r"(b1));
}

__device__ __forceinline__ uint32_t pack2(bf16 a, bf16 b) {
    return ((uint32_t)__bfloat16_as_ushort(b) << 16) | (uint32_t)__bfloat16_as_ushort(a);
}

// ---------------- small kernels ------------------------------------------------
__global__ void zero_counts_kernel() {
    if (threadIdx.x < NEXP) g_cnt[threadIdx.x] = 0;
}

__global__ void cvtx_kernel(const float* __restrict__ in,
                            bf16* __restrict__ oh, bf16* __restrict__ ol, int n4) {
    int i = blockIdx.x * blockDim.x + threadIdx.x;
    if (i >= n4) return;
    float4 v = reinterpret_cast<const float4*>(in)[i];
    bf16 h0 = __float2bfloat16(v.x), h1 = __float2bfloat16(v.y);
    bf16 h2 = __float2bfloat16(v.z), h3 = __float2bfloat16(v.w);
    bf16 l0 = __float2bfloat16(v.x - __bfloat162float(h0));
    bf16 l1 = __float2bfloat16(v.y - __bfloat162float(h1));
    bf16 l2 = __float2bfloat16(v.z - __bfloat162float(h2));
    bf16 l3 = __float2bfloat16(v.w - __bfloat162float(h3));
    uint2 ph; ph.x = pack2(h0, h1); ph.y = pack2(h2, h3);
    uint2 pl; pl.x = pack2(l0, l1); pl.y = pack2(l2, l3);
    reinterpret_cast<uint2*>(oh)[i] = ph;
    reinterpret_cast<uint2*>(ol)[i] = pl;
}

// transpose+split: in [z][K][N] f32 -> oh/ol [z][N][K] bf16
__global__ void cvtT_kernel(const float* __restrict__ in,
                            bf16* __restrict__ oh, bf16* __restrict__ ol,
                            int K, int N) {
    __shared__ float tile[32][33];
    size_t z = blockIdx.z;
    in += z * (size_t)K * N;
    oh += z * (size_t)N * K;
    ol += z * (size_t)N * K;
    int k0 = blockIdx.y * 32, n0 = blockIdx.x * 32;
    int tx = threadIdx.x, ty = threadIdx.y;
#pragma unroll
    for (int i = 0; i < 32; i += 8)
        tile[ty + i][tx] = in[(size_t)(k0 + ty + i) * N + (n0 + tx)];
    __syncthreads();
#pragma unroll
    for (int i = 0; i < 32; i += 8) {
        float v = tile[tx][ty + i];
        bf16 h = __float2bfloat16(v);
        bf16 l = __float2bfloat16(v - __bfloat162float(h));
        size_t idx = (size_t)(n0 + ty + i) * K + (k0 + tx);
        oh[idx] = h;  ol[idx] = l;
    }
}

__global__ void gate_kernel(const float* __restrict__ x, const float* __restrict__ gw) {
    int tok  = (blockIdx.x * blockDim.x + threadIdx.x) >> 5;
    int lane = threadIdx.x & 31;
    if (tok >= TOK) return;
    const float* xr = x + (size_t)tok * DIM;
    float acc[NEXP];
#pragma unroll
    for (int e = 0; e < NEXP; e++) acc[e] = 0.f;
    for (int d = lane; d < DIM; d += 32) {
        float xv = xr[d];
#pragma unroll
        for (int e = 0; e < NEXP; e++) acc[e] = fmaf(xv, gw[e * DIM + d], acc[e]);
    }
#pragma unroll
    for (int e = 0; e < NEXP; e++)
#pragma unroll
        for (int off = 16; off > 0; off >>= 1)
            acc[e] += __shfl_xor_sync(0xffffffffu, acc[e], off);
    if (lane == 0) {
        float mx = acc[0];
#pragma unroll
        for (int e = 1; e < NEXP; e++) mx = fmaxf(mx, acc[e]);
        float p[NEXP], s = 0.f;
#pragma unroll
        for (int e = 0; e < NEXP; e++) { p[e] = expf(acc[e] - mx); s += p[e]; }
        float inv = 1.f / s;
#pragma unroll
        for (int e = 0; e < NEXP; e++) p[e] *= inv;
        int i1 = 0;
#pragma unroll
        for (int e = 1; e < NEXP; e++) if (p[e] > p[i1]) i1 = e;
        int i2 = (i1 == 0) ? 1 : 0;
#pragma unroll
        for (int e = 0; e < NEXP; e++) if (e != i1 && p[e] > p[i2]) i2 = e;
        int pos1 = atomicAdd(&g_cnt[i1], 1);
        g_idx[i1 * TOK + pos1] = tok;  g_wgt[i1 * TOK + pos1] = p[i1];
        g_slot[2 * tok] = i1 * TOK + pos1;
        int pos2 = atomicAdd(&g_cnt[i2], 1);
        g_idx[i2 * TOK + pos2] = tok;  g_wgt[i2 * TOK + pos2] = p[i2];
        g_slot[2 * tok + 1] = i2 * TOK + pos2;
    }
}

// ---------------- GEMM1: fused SwiGLU up-proj ---------------------------------
// BM=128, BN=64 (per B-matrix), BK=32, 256 threads (8 warps: 2m x 4n).
// Stage layout (bf16 units): Ah[128*40] Al[128*40] B1h[64*40] B1l B3h B3l
#define G1_S_AH   0
#define G1_S_AL   5120
#define G1_S_B1H  10240
#define G1_S_B1L  12800
#define G1_S_B3H  15360
#define G1_S_B3L  17920
#define G1_STG    20480
#define G1_SMEM   (2 * G1_STG * 2)   // 81920 B

__global__ void __launch_bounds__(256)
gemm1_kernel(const bf16* __restrict__ Xh, const bf16* __restrict__ Xl,
             const bf16* __restrict__ B1h, const bf16* __restrict__ B1l,
             const bf16* __restrict__ B3h, const bf16* __restrict__ B3l,
             bf16* __restrict__ Hh, bf16* __restrict__ Hl,
             int routed, int N) {
    const int K = DIM;
    int e = routed ? (int)blockIdx.z : 0;
    int M = routed ? g_cnt[e] : TOK;
    int rowBlock = blockIdx.y * 128;
    if (rowBlock >= M) return;
    int colBlock = blockIdx.x * 64;
    if (routed) {
        size_t wo = (size_t)e * N * K;
        B1h += wo; B1l += wo; B3h += wo; B3l += wo;
        Hh += (size_t)e * TOK * N;  Hl += (size_t)e * TOK * N;
    }

    extern __shared__ __align__(16) bf16 sm1[];
    uint32_t sb0 = smem_u32(sm1);

    int tid = threadIdx.x, lane = tid & 31, warp = tid >> 5;
    int wm = warp >> 2, wn = warp & 3;

    // ---- global load mapping ----
    int ra = tid >> 1, ka = (tid & 1) * 16;       // A: 1 row per thread, 2 chunks
    bool aval = (rowBlock + ra) < M;
    int asrc = aval ? (routed ? g_idx[e * TOK + rowBlock + ra] : rowBlock + ra) : 0;
    const bf16* aph = Xh + (size_t)asrc * K + ka;
    const bf16* apl = Xl + (size_t)asrc * K + ka;
    uint32_t adst = (uint32_t)(ra * LDH + ka) * 2;

    int rb = tid >> 2, kb = (tid & 3) * 8;        // B: 64 rows, 1 chunk/thread/matrix
    const bf16* b1ph = B1h + (size_t)(colBlock + rb) * K + kb;
    const bf16* b1pl = B1l + (size_t)(colBlock + rb) * K + kb;
    const bf16* b3ph = B3h + (size_t)(colBlock + rb) * K + kb;
    const bf16* b3pl = B3l + (size_t)(colBlock + rb) * K + kb;
    uint32_t bdst = (uint32_t)(rb * LDH + kb) * 2;

    auto load_stage = [&](int s, int k0) {
        uint32_t sb = sb0 + (uint32_t)s * G1_STG * 2;
        cp16(sb + G1_S_AH * 2 + adst,      aph + k0,     aval);
        cp16(sb + G1_S_AH * 2 + adst + 16, aph + k0 + 8, aval);
        cp16(sb + G1_S_AL * 2 + adst,      apl + k0,     aval);
        cp16(sb + G1_S_AL * 2 + adst + 16, apl + k0 + 8, aval);
        cp16(sb + G1_S_B1H * 2 + bdst, b1ph + k0, true);
        cp16(sb + G1_S_B1L * 2 + bdst, b1pl + k0, true);
        cp16(sb + G1_S_B3H * 2 + bdst, b3ph + k0, true);
        cp16(sb + G1_S_B3L * 2 + bdst, b3pl + k0, true);
    };

    // ---- ldmatrix address bases (bf16-element units) ----
    int lrow = lane & 15, lkA = (lane >> 4) * 8;
    uint32_t aOffH[4], aOffL[4];
#pragma unroll
    for (int mi = 0; mi < 4; mi++) {
        int r = wm * 64 + mi * 16 + lrow;
        aOffH[mi] = (uint32_t)(G1_S_AH + r * LDH + lkA) * 2;
        aOffL[mi] = (uint32_t)(G1_S_AL + r * LDH + lkA) * 2;
    }
    int nloc = (lane & 7) | ((lane & 16) >> 1);
    int lkB  = ((lane >> 3) & 1) * 8;
    uint32_t bRow = (uint32_t)((wn * 16 + nloc) * LDH + lkB) * 2;
    uint32_t b1OffH = G1_S_B1H * 2 + bRow, b1OffL = G1_S_B1L * 2 + bRow;
    uint32_t b3OffH = G1_S_B3H * 2 + bRow, b3OffL = G1_S_B3L * 2 + bRow;

    float acc1[4][2][4], acc3[4][2][4];
#pragma unroll
    for (int i = 0; i < 4; i++)
#pragma unroll
        for (int j = 0; j < 2; j++)
#pragma unroll
            for (int r = 0; r < 4; r++) { acc1[i][j][r] = 0.f; acc3[i][j][r] = 0.f; }

    load_stage(0, 0);
    CP_COMMIT();
    const int nIter = K / 32;
    for (int i = 0; i < nIter; i++) {
        if (i + 1 < nIter) { load_stage((i + 1) & 1, (i + 1) * 32); CP_COMMIT(); CP_WAIT1(); }
        else               { CP_WAIT0(); }
        __syncthreads();
        uint32_t sb = sb0 + (uint32_t)(i & 1) * G1_STG * 2;
#pragma unroll
        for (int ks = 0; ks < 2; ks++) {
            uint32_t ko = (uint32_t)ks * 32;   // 16 bf16 = 32 bytes
            uint32_t ah[4][4], al[4][4];
#pragma unroll
            for (int mi = 0; mi < 4; mi++) {
                LDSM4(ah[mi], sb + aOffH[mi] + ko);
                LDSM4(al[mi], sb + aOffL[mi] + ko);
            }
            uint32_t b1h[4], b1l[4], b3h[4], b3l[4];
            LDSM4(b1h, sb + b1OffH + ko);
            LDSM4(b1l, sb + b1OffL + ko);
            LDSM4(b3h, sb + b3OffH + ko);
            LDSM4(b3l, sb + b3OffL + ko);
#pragma unroll
            for (int mi = 0; mi < 4; mi++)
#pragma unroll
                for (int nf = 0; nf < 2; nf++) {
                    mma_bf16(acc1[mi][nf], ah[mi], b1h[2*nf], b1h[2*nf+1]);
                    mma_bf16(acc1[mi][nf], al[mi], b1h[2*nf], b1h[2*nf+1]);
                    mma_bf16(acc1[mi][nf], ah[mi], b1l[2*nf], b1l[2*nf+1]);
                    mma_bf16(acc3[mi][nf], ah[mi], b3h[2*nf], b3h[2*nf+1]);
                    mma_bf16(acc3[mi][nf], al[mi], b3h[2*nf], b3h[2*nf+1]);
                    mma_bf16(acc3[mi][nf], ah[mi], b3l[2*nf], b3l[2*nf+1]);
                }
        }
        __syncthreads();
    }

    // ---- epilogue: silu(acc1)*acc3, split hi/lo, store ----
    int rr = lane >> 2, cc = (lane & 3) * 2;
#pragma unroll
    for (int mi = 0; mi < 4; mi++) {
        int gmb = rowBlock + wm * 64 + mi * 16 + rr;
#pragma unroll
        for (int nf = 0; nf < 2; nf++) {
            int col = colBlock + wn * 16 + nf * 8 + cc;
#pragma unroll
            for (int hf = 0; hf < 2; hf++) {
                int gm = gmb + hf * 8;
                if (gm < M) {
                    float v1a = acc1[mi][nf][hf*2], v1b = acc1[mi][nf][hf*2+1];
                    float v3a = acc3[mi][nf][hf*2], v3b = acc3[mi][nf][hf*2+1];
                    float h0 = v1a / (1.f + expf(-v1a)) * v3a;
                    float h1 = v1b / (1.f + expf(-v1b)) * v3b;
                    bf16 hh0 = __float2bfloat16(h0), hh1 = __float2bfloat16(h1);
                    bf16 ll0 = __float2bfloat16(h0 - __bfloat162float(hh0));
                    bf16 ll1 = __float2bfloat16(h1 - __bfloat162float(hh1));
                    *reinterpret_cast<uint32_t*>(Hh + (size_t)gm * N + col) = pack2(hh0, hh1);
                    *reinterpret_cast<uint32_t*>(Hl + (size_t)gm * N + col) = pack2(ll0, ll1);
                }
            }
        }
    }
}

// ---------------- GEMM2: down-projection --------------------------------------
// BM=128, BN=128, BK=32, 256 threads (8 warps: 2m x 4n, warp tile 64x32).
#define G2_S_AH  0
#define G2_S_AL  5120
#define G2_S_BH  10240
#define G2_S_BL  15360
#define G2_STG   20480
#define G2_SMEM  (2 * G2_STG * 2)    // 81920 B

__global__ void __launch_bounds__(256)
gemm2_kernel(const bf16* __restrict__ Ah, const bf16* __restrict__ Al,
             const bf16* __restrict__ Bh, const bf16* __restrict__ Bl,
             float* __restrict__ Y, int routed, int K) {
    int e = routed ? (int)blockIdx.z : 0;
    int M = routed ? g_cnt[e] : TOK;
    int rowBlock = blockIdx.y * 128;
    if (rowBlock >= M) return;
    int colBlock = blockIdx.x * 128;
    if (routed) {
        Ah += (size_t)e * TOK * K;  Al += (size_t)e * TOK * K;
        Bh += (size_t)e * DIM * K;  Bl += (size_t)e * DIM * K;
        Y  += (size_t)e * TOK * DIM;
    }

    extern __shared__ __align__(16) bf16 sm2[];
    uint32_t sb0 = smem_u32(sm2);

    int tid = threadIdx.x, lane = tid & 31, warp = tid >> 5;
    int wm = warp >> 2, wn = warp & 3;

    int ra = tid >> 1, ka = (tid & 1) * 16;
    bool aval = (rowBlock + ra) < M;
    const bf16* aph = Ah + (size_t)(aval ? rowBlock + ra : 0) * K + ka;
    const bf16* apl = Al + (size_t)(aval ? rowBlock + ra : 0) * K + ka;
    uint32_t adst = (uint32_t)(ra * LDH + ka) * 2;

    const bf16* bph = Bh + (size_t)(colBlock + ra) * K + ka;
    const bf16* bpl = Bl + (size_t)(colBlock + ra) * K + ka;

    auto load_stage = [&](int s, int k0) {
        uint32_t sb = sb0 + (uint32_t)s * G2_STG * 2;
        cp16(sb + G2_S_AH * 2 + adst,      aph + k0,     aval);
        cp16(sb + G2_S_AH * 2 + adst + 16, aph + k0 + 8, aval);
        cp16(sb + G2_S_AL * 2 + adst,      apl + k0,     aval);
        cp16(sb + G2_S_AL * 2 + adst + 16, apl + k0 + 8, aval);
        cp16(sb + G2_S_BH * 2 + adst,      bph + k0,     true);
        cp16(sb + G2_S_BH * 2 + adst + 16, bph + k0 + 8, true);
        cp16(sb + G2_S_BL * 2 + adst,      bpl + k0,     true);
        cp16(sb + G2_S_BL * 2 + adst + 16, bpl + k0 + 8, true);
    };

    int lrow = lane & 15, lkA = (lane >> 4) * 8;
    uint32_t aOffH[4], aOffL[4];
#pragma unroll
    for (int mi = 0; mi < 4; mi++) {
        int r = wm * 64 + mi * 16 + lrow;
        aOffH[mi] = (uint32_t)(G2_S_AH + r * LDH + lkA) * 2;
        aOffL[mi] = (uint32_t)(G2_S_AL + r * LDH + lkA) * 2;
    }
    int nloc = (lane & 7) | ((lane & 16) >> 1);
    int lkB  = ((lane >> 3) & 1) * 8;
    uint32_t bOffH[2], bOffL[2];
#pragma unroll
    for (int ng = 0; ng < 2; ng++) {
        int n = wn * 32 + ng * 16 + nloc;
        bOffH[ng] = (uint32_t)(G2_S_BH + n * LDH + lkB) * 2;
        bOffL[ng] = (uint32_t)(G2_S_BL + n * LDH + lkB) * 2;
    }

    float acc[4][4][4];
#pragma unroll
    for (int i = 0; i < 4; i++)
#pragma unroll
        for (int j = 0; j < 4; j++)
#pragma unroll
            for (int r = 0; r < 4; r++) acc[i][j][r] = 0.f;

    load_stage(0, 0);
    CP_COMMIT();
    const int nIter = K / 32;
    for (int i = 0; i < nIter; i++) {
        if (i + 1 < nIter) { load_stage((i + 1) & 1, (i + 1) * 32); CP_COMMIT(); CP_WAIT1(); }
        else               { CP_WAIT0(); }
        __syncthreads();
        uint32_t sb = sb0 + (uint32_t)(i & 1) * G2_STG * 2;
#pragma unroll
        for (int ks = 0; ks < 2; ks++) {
            uint32_t ko = (uint32_t)ks * 32;
            uint32_t ah[4][4], al[4][4];
#pragma unroll
            for (int mi = 0; mi < 4; mi++) {
                LDSM4(ah[mi], sb + aOffH[mi] + ko);
                LDSM4(al[mi], sb + aOffL[mi] + ko);
            }
            uint32_t bh[2][4], bl[2][4];
#pragma unroll
            for (int ng = 0; ng < 2; ng++) {
                LDSM4(bh[ng], sb + bOffH[ng] + ko);
                LDSM4(bl[ng], sb + bOffL[ng] + ko);
            }
#pragma unroll
            for (int mi = 0; mi < 4; mi++)
#pragma unroll
                for (int nf = 0; nf < 4; nf++) {
                    uint32_t h0 = bh[nf >> 1][(nf & 1) * 2], h1 = bh[nf >> 1][(nf & 1) * 2 + 1];
                    uint32_t l0 = bl[nf >> 1][(nf & 1) * 2], l1 = bl[nf >> 1][(nf & 1) * 2 + 1];
                    mma_bf16(acc[mi][nf], ah[mi], h0, h1);
                    mma_bf16(acc[mi][nf], al[mi], h0, h1);
                    mma_bf16(acc[mi][nf], ah[mi], l0, l1);
                }
        }
        __syncthreads();
    }

    int rr = lane >> 2, cc = (lane & 3) * 2;
#pragma unroll
    for (int mi = 0; mi < 4; mi++) {
        int gmb = rowBlock + wm * 64 + mi * 16 + rr;
#pragma unroll
        for (int hf = 0; hf < 2; hf++) {
            int gm = gmb + hf * 8;
            if (gm < M) {
                float w = routed ? g_wgt[e * TOK + gm] : 1.0f;
                float* dst = Y + (size_t)gm * DIM;
#pragma unroll
                for (int nf = 0; nf < 4; nf++) {
                    int col = colBlock + wn * 32 + nf * 8 + cc;
                    float2 v;
                    v.x = w * acc[mi][nf][hf*2];
                    v.y = w * acc[mi][nf][hf*2+1];
                    *reinterpret_cast<float2*>(dst + col) = v;
                }
            }
        }
    }
}

// out[t] += yp[slot0(t)] + yp[slot1(t)]
__global__ void combine_kernel(float* __restrict__ out) {
    int t = blockIdx.x;
    int d = threadIdx.x;
    int s0 = g_slot[2 * t], s1 = g_slot[2 * t + 1];
    float4* o = reinterpret_cast<float4*>(out) + (size_t)t * 256 + d;
    const float4 a  = *o;
    const float4 b0 = reinterpret_cast<const float4*>(g_yp)[(size_t)s0 * 256 + d];
    const float4 b1 = reinterpret_cast<const float4*>(g_yp)[(size_t)s1 * 256 + d];
    float4 r;
    r.x = a.x + (b0.x + b1.x);
    r.y = a.y + (b0.y + b1.y);
    r.z = a.z + (b0.z + b1.z);
    r.w = a.w + (b0.w + b1.w);
    *o = r;
}

// ---------------- launcher -----------------------------------------------------
extern "C" void kernel_launch(void* const* d_in, const int* in_sizes, int n_in,
                              void* d_out, int out_size) {
    const float* x   = (const float*)d_in[0];
    const float* gw  = (const float*)d_in[1];
    const float* w1  = (const float*)d_in[2];
    const float* w2  = (const float*)d_in[3];
    const float* w3  = (const float*)d_in[4];
    const float* sw1 = (const float*)d_in[5];
    const float* sw2 = (const float*)d_in[6];
    const float* sw3 = (const float*)d_in[7];
    float* out = (float*)d_out;
    (void)in_sizes; (void)n_in; (void)out_size;

    cudaFuncSetAttribute(gemm1_kernel, cudaFuncAttributeMaxDynamicSharedMemorySize, G1_SMEM);
    cudaFuncSetAttribute(gemm2_kernel, cudaFuncAttributeMaxDynamicSharedMemorySize, G2_SMEM);

    bf16 *xh, *xl, *w1h, *w1l, *w3h, *w3l, *w2h, *w2l;
    bf16 *s1h, *s1l, *s3h, *s3l, *s2h, *s2l, *hh, *hl, *hsh, *hsl;
    float* yp;
    cudaGetSymbolAddress((void**)&xh,  g_xh);  cudaGetSymbolAddress((void**)&xl,  g_xl);
    cudaGetSymbolAddress((void**)&w1h, g_w1h); cudaGetSymbolAddress((void**)&w1l, g_w1l);
    cudaGetSymbolAddress((void**)&w3h, g_w3h); cudaGetSymbolAddress((void**)&w3l, g_w3l);
    cudaGetSymbolAddress((void**)&w2h, g_w2h); cudaGetSymbolAddress((void**)&w2l, g_w2l);
    cudaGetSymbolAddress((void**)&s1h, g_s1h); cudaGetSymbolAddress((void**)&s1l, g_s1l);
    cudaGetSymbolAddress((void**)&s3h, g_s3h); cudaGetSymbolAddress((void**)&s3l, g_s3l);
    cudaGetSymbolAddress((void**)&s2h, g_s2h); cudaGetSymbolAddress((void**)&s2l, g_s2l);
    cudaGetSymbolAddress((void**)&hh,  g_hh);  cudaGetSymbolAddress((void**)&hl,  g_hl);
    cudaGetSymbolAddress((void**)&hsh, g_hsh); cudaGetSymbolAddress((void**)&hsl, g_hsl);
    cudaGetSymbolAddress((void**)&yp,  g_yp);

    zero_counts_kernel<<<1, 32>>>();
    cvtx_kernel<<<(TOK * DIM / 4 + 255) / 256, 256>>>(x, xh, xl, TOK * DIM / 4);
    cvtT_kernel<<<dim3(EHID / 32, DIM / 32, NEXP), dim3(32, 8)>>>(w1, w1h, w1l, DIM, EHID);
    cvtT_kernel<<<dim3(EHID / 32, DIM / 32, NEXP), dim3(32, 8)>>>(w3, w3h, w3l, DIM, EHID);
    cvtT_kernel<<<dim3(DIM / 32, EHID / 32, NEXP), dim3(32, 8)>>>(w2, w2h, w2l, EHID, DIM);
    cvtT_kernel<<<dim3(SHID / 32, DIM / 32, 1),  dim3(32, 8)>>>(sw1, s1h, s1l, DIM, SHID);
    cvtT_kernel<<<dim3(SHID / 32, DIM / 32, 1),  dim3(32, 8)>>>(sw3, s3h, s3l, DIM, SHID);
    cvtT_kernel<<<dim3(DIM / 32, SHID / 32, 1),  dim3(32, 8)>>>(sw2, s2h, s2l, SHID, DIM);
    gate_kernel<<<TOK / 8, 256>>>(x, gw);

    // shared expert (initializes d_out)
    gemm1_kernel<<<dim3(SHID / 64, TOK / 128, 1), 256, G1_SMEM>>>(
        xh, xl, s1h, s1l, s3h, s3l, hsh, hsl, 0, SHID);
    gemm2_kernel<<<dim3(DIM / 128, TOK / 128, 1), 256, G2_SMEM>>>(
        hsh, hsl, s2h, s2l, out, 0, SHID);

    // routed experts, batched over grid.z
    gemm1_kernel<<<dim3(EHID / 64, TOK / 128, NEXP), 256, G1_SMEM>>>(
        xh, xl, w1h, w1l, w3h, w3l, hh, hl, 1, EHID);
    gemm2_kernel<<<dim3(DIM / 128, TOK / 128, NEXP), 256, G2_SMEM>>>(
        hh, hl, w2h, w2l, yp, 1, EHID);

    combine_kernel<<<TOK, 256>>>(out);
}